// round 9
// baseline (speedup 1.0000x reference)
#include <cuda_runtime.h>
#include <cuda_bf16.h>
#include <math.h>
#include <stdint.h>

#define SEQ    80
#define BATCH  256
#define EMBED  100
#define UNITS  2048
#define WK     4096          // weight row: [hi(2048) | lo(2048)]
#define XK     256           // x row: [hi(128 pad) | lo(128 pad)]
#define HROW   8192          // h row: [h0hi|h0lo|h1hi|h1lo]
#define NCTA   128

// ---------------- scratch ----------------------------------------------------
__device__ __nv_bfloat16 g_xe [SEQ * BATCH * XK];
__device__ __nv_bfloat16 g_w0t[UNITS * XK];
__device__ __nv_bfloat16 g_U0t[UNITS * WK];
__device__ __nv_bfloat16 g_W1t[UNITS * WK];
__device__ __nv_bfloat16 g_U1t[UNITS * WK];
__device__ float g_xw0[SEQ * BATCH * UNITS];
__device__ float g_p  [BATCH * UNITS];             // p = h1 @ U1 (fp32)
__device__ __nv_bfloat16 g_hbuf[2][BATCH * HROW];
__device__ float g_h1f[BATCH * UNITS];
__device__ unsigned g_bar[2 * SEQ + 8];            // grid-barrier counters

// ---------------- PTX helpers -------------------------------------------------
__device__ __forceinline__ uint32_t smem_u32(const void* p) {
    uint32_t a;
    asm("{ .reg .u64 t; cvta.to.shared.u64 t, %1; cvt.u32.u64 %0, t; }" : "=r"(a) : "l"(p));
    return a;
}
#define CP_ASYNC16(sp, gp) \
    asm volatile("cp.async.cg.shared.global [%0], [%1], 16;" :: "r"(sp), "l"(gp))
#define CP_COMMIT()  asm volatile("cp.async.commit_group;")
#define CP_WAIT1()   asm volatile("cp.async.wait_group 1;")
#define CP_WAIT0()   asm volatile("cp.async.wait_group 0;")

__device__ __forceinline__ void ldm_x4(uint32_t* r, uint32_t addr) {
    asm volatile("ldmatrix.sync.aligned.m8n8.x4.shared.b16 {%0,%1,%2,%3}, [%4];"
                 : "=r"(r[0]), "=r"(r[1]), "=r"(r[2]), "=r"(r[3]) : "r"(addr));
}
__device__ __forceinline__ void mma_bf16(float* d, const uint32_t* a, const uint32_t* b) {
    asm volatile("mma.sync.aligned.m16n8k16.row.col.f32.bf16.bf16.f32 "
                 "{%0,%1,%2,%3}, {%4,%5,%6,%7}, {%8,%9}, {%0,%1,%2,%3};"
                 : "+f"(d[0]), "+f"(d[1]), "+f"(d[2]), "+f"(d[3])
                 : "r"(a[0]), "r"(a[1]), "r"(a[2]), "r"(a[3]), "r"(b[0]), "r"(b[1]));
}

__device__ __forceinline__ int swz128(int row, int c16) {
    return row * 128 + ((c16 ^ (row & 7)) << 4);
}

// grid-wide barrier: one counter slot per use, all NCTA CTAs must arrive.
__device__ __forceinline__ void grid_sync(unsigned* bar, int s) {
    __syncthreads();
    if (threadIdx.x == 0) {
        __threadfence();
        atomicAdd(&bar[s], 1u);
        while (*((volatile unsigned*)&bar[s]) < NCTA) __nanosleep(32);
    }
    __syncthreads();
}

// ---------------- split-GEMM tile (3-term hi/lo, warp-group K-split) ----------
struct Args {
    const __nv_bfloat16 *Ahi, *Alo, *Bhi, *Blo;
    int  nchunk;                  // K / 64 (even)
    long lda, ldb;
    const float* addend;          // [M,2048] or null (read via __ldcg)
    const float* bias;            // [2048] or null
    __nv_bfloat16* outE;          // hi @ col n, lo @ col n+2048; or null
    long ldo;
    float* out32;                 // [M,2048] or null
    int  act;
};

template<int NROWS>
__device__ __forceinline__ void load_rows(const __nv_bfloat16* src, long ld,
                                          int rbase, int kc, char* dst, int tl) {
    #pragma unroll
    for (int i = 0; i < NROWS * 8 / 256; i++) {
        int s = tl + i * 256;
        int row = s >> 3, c16 = s & 7;
        const void* g = src + (size_t)(rbase + row) * ld + kc * 64 + c16 * 8;
        CP_ASYNC16(smem_u32(dst + swz128(row, c16)), g);
    }
}

// BM=64. 512 threads = 16 warps: kg = wid>>3 (k-group), w8 = wid&7 as 2m x 4n.
// Superchunk BK=128: kg0 computes 64-col sub-chunk 0, kg1 sub-chunk 1, into
// independent accumulators; reduced via SMEM once at the end.
template<int BN>
__device__ void gemm_tile(const Args& g, int cm, int cn, char* sm)
{
    constexpr int NI = BN / 64;
    constexpr int TILE_A = 64 * 128;
    constexpr int TILE_B = BN * 128;
    constexpr int SUB    = 2 * TILE_A + 2 * TILE_B;   // one 64-col sub-chunk set
    constexpr int STAGE  = 2 * SUB;                   // superchunk (BK=128)
    constexpr int NF     = 2 * 2 * NI * 4;            // acc floats per thread

    int tid  = threadIdx.x;
    int lane = tid & 31;
    int wid  = tid >> 5;
    int kg   = wid >> 3;          // 0..1 k-group
    int w8   = wid & 7;
    int wm   = w8 >> 2;
    int wn   = w8 & 3;

    float acc[2][2 * NI][4];
    #pragma unroll
    for (int i = 0; i < 2; i++)
        #pragma unroll
        for (int j = 0; j < 2 * NI; j++)
            #pragma unroll
            for (int k = 0; k < 4; k++) acc[i][j][k] = 0.f;

    int NCS = g.nchunk >> 1;      // superchunks

    auto issue = [&](int sc) {
        int sub = tid >> 8;       // 0..1: which sub-chunk this half-block loads
        int tl  = tid & 255;
        char* st = sm + (sc & 1) * STAGE + sub * SUB;
        int c2 = 2 * sc + sub;
        load_rows<64>(g.Ahi, g.lda, cm, c2, st,              tl);
        load_rows<64>(g.Alo, g.lda, cm, c2, st + TILE_A,     tl);
        load_rows<BN>(g.Bhi, g.ldb, cn, c2, st + 2 * TILE_A, tl);
        load_rows<BN>(g.Blo, g.ldb, cn, c2, st + 2 * TILE_A + TILE_B, tl);
        CP_COMMIT();
    };

    issue(0);

    for (int sc = 0; sc < NCS; sc++) {
        if (sc + 1 < NCS) { issue(sc + 1); CP_WAIT1(); } else { CP_WAIT0(); }
        __syncthreads();

        char* cs = sm + (sc & 1) * STAGE + kg * SUB;
        char* pa_hi = cs;
        char* pa_lo = cs + TILE_A;
        char* pb_hi = cs + 2 * TILE_A;
        char* pb_lo = cs + 2 * TILE_A + TILE_B;

        #pragma unroll
        for (int ks = 0; ks < 4; ks++) {
            uint32_t ahi[2][4], alo[2][4], bhi[NI][4], blo[NI][4];
            #pragma unroll
            for (int mi = 0; mi < 2; mi++) {
                int arow = wm * 32 + mi * 16 + (lane & 15);
                int ac   = ks * 2 + (lane >> 4);
                ldm_x4(ahi[mi], smem_u32(pa_hi + swz128(arow, ac)));
                ldm_x4(alo[mi], smem_u32(pa_lo + swz128(arow, ac)));
            }
            #pragma unroll
            for (int np = 0; np < NI; np++) {
                int brow = wn * (BN / 4) + np * 16 + ((lane & 16) ? 8 : 0) + (lane & 7);
                int bc   = ks * 2 + ((lane >> 3) & 1);
                ldm_x4(bhi[np], smem_u32(pb_hi + swz128(brow, bc)));
                ldm_x4(blo[np], smem_u32(pb_lo + swz128(brow, bc)));
            }
            #pragma unroll
            for (int mi = 0; mi < 2; mi++)
                #pragma unroll
                for (int np = 0; np < NI; np++)
                    #pragma unroll
                    for (int h = 0; h < 2; h++) {
                        float* a_ = acc[mi][np * 2 + h];
                        mma_bf16(a_, ahi[mi], &bhi[np][h * 2]);
                        mma_bf16(a_, alo[mi], &bhi[np][h * 2]);
                        mma_bf16(a_, ahi[mi], &blo[np][h * 2]);
                    }
        }
        __syncthreads();   // all warps done with stage (sc&1) before it is re-issued
    }

    // K-group reduction through SMEM (stage memory is free now)
    float* red = (float*)sm;
    int t8 = tid & 255;
    if (kg == 1) {
        #pragma unroll
        for (int mi = 0; mi < 2; mi++)
            #pragma unroll
            for (int ni = 0; ni < 2 * NI; ni++)
                #pragma unroll
                for (int k = 0; k < 4; k++)
                    red[t8 * NF + (mi * 2 * NI + ni) * 4 + k] = acc[mi][ni][k];
    }
    __syncthreads();
    if (kg == 1) return;           // kg0 warps own the epilogue
    #pragma unroll
    for (int mi = 0; mi < 2; mi++)
        #pragma unroll
        for (int ni = 0; ni < 2 * NI; ni++)
            #pragma unroll
            for (int k = 0; k < 4; k++)
                acc[mi][ni][k] += red[t8 * NF + (mi * 2 * NI + ni) * 4 + k];

    // epilogue (kg0: 8 warps, identical mapping to the 256-thread version)
    int r0 = cm + wm * 32 + (lane >> 2);
    int c0 = cn + wn * (BN / 4) + (lane & 3) * 2;
    #pragma unroll
    for (int mi = 0; mi < 2; mi++) {
        #pragma unroll
        for (int ni = 0; ni < 2 * NI; ni++) {
            #pragma unroll
            for (int h8 = 0; h8 < 2; h8++) {
                int row = r0 + mi * 16 + h8 * 8;
                int col = c0 + ni * 8;
                float v0 = acc[mi][ni][h8 * 2 + 0];
                float v1 = acc[mi][ni][h8 * 2 + 1];
                if (g.addend) {
                    float2 ad = __ldcg((const float2*)&g.addend[(size_t)row * UNITS + col]);
                    v0 += ad.x; v1 += ad.y;
                }
                if (g.bias) {
                    float2 bi = *(const float2*)&g.bias[col];
                    v0 += bi.x; v1 += bi.y;
                }
                if (g.act) { v0 = tanhf(v0); v1 = tanhf(v1); }
                if (g.out32)
                    *(float2*)&g.out32[(size_t)row * UNITS + col] = make_float2(v0, v1);
                if (g.outE) {
                    __nv_bfloat16 h0 = __float2bfloat16(v0);
                    __nv_bfloat16 h1 = __float2bfloat16(v1);
                    __nv_bfloat16 l0 = __float2bfloat16(v0 - __bfloat162float(h0));
                    __nv_bfloat16 l1 = __float2bfloat16(v1 - __bfloat162float(h1));
                    __nv_bfloat162 hp; hp.x = h0; hp.y = h1;
                    __nv_bfloat162 lp; lp.x = l0; lp.y = l1;
                    *(__nv_bfloat162*)&g.outE[(size_t)row * g.ldo + col]         = hp;
                    *(__nv_bfloat162*)&g.outE[(size_t)row * g.ldo + UNITS + col] = lp;
                }
            }
        }
    }
}

// ---------------- standalone GEMM kernel (xw0 precompute) ---------------------
__global__ void __launch_bounds__(512)
xw0_gemm(Args g)
{
    extern __shared__ __align__(16) char sm[];
    gemm_tile<128>(g, blockIdx.y * 64, blockIdx.x * 128, sm);
}

// ---------------- persistent RNN time loop ------------------------------------
__global__ void __launch_bounds__(512)
rnn_persistent(const __nv_bfloat16* __restrict__ U0t,
               const __nv_bfloat16* __restrict__ W1t,
               const __nv_bfloat16* __restrict__ U1t,
               const float* __restrict__ xw0,
               const float* __restrict__ b1,
               float* __restrict__ pbuf,
               __nv_bfloat16* __restrict__ hbuf,
               float* __restrict__ h1f,
               unsigned* __restrict__ bar)
{
    extern __shared__ __align__(16) char sm[];
    int cid = blockIdx.x;

    __nv_bfloat16* cur = hbuf;
    __nv_bfloat16* nxt = hbuf + (size_t)BATCH * HROW;

    for (int t = 0; t < SEQ; t++) {
        // phase A: 64 CTAs -> h0' = tanh(xw0_t + h0@U0); 64 CTAs -> p = h1@U1
        {
            int unit = cid >> 6;
            int id   = cid & 63;
            int cm = (id >> 4) * 64;     // 0..3 -> 4 m-tiles
            int cn = (id & 15) * 128;    // 0..15 -> 16 n-tiles

            Args g{};
            g.nchunk = UNITS / 64; g.lda = HROW; g.ldb = WK;
            if (unit == 0) {
                g.Ahi = cur;  g.Alo = cur + 2048;
                g.Bhi = U0t;  g.Blo = U0t + 2048;
                g.addend = xw0 + (size_t)t * BATCH * UNITS; g.bias = nullptr;
                g.outE = nxt; g.ldo = HROW; g.out32 = nullptr; g.act = 1;
            } else {
                g.Ahi = cur + 4096; g.Alo = cur + 6144;
                g.Bhi = U1t;        g.Blo = U1t + 2048;
                g.addend = nullptr; g.bias = nullptr;
                g.outE = nullptr; g.ldo = 0; g.out32 = pbuf; g.act = 0;
            }
            gemm_tile<128>(g, cm, cn, sm);
        }
        grid_sync(bar, 2 * t);

        // phase B: 128 CTAs -> h1' = tanh(h0'@W1 + p + b1)
        {
            int cm = (cid >> 5) * 64;    // 0..3
            int cn = (cid & 31) * 64;    // 0..31

            Args g{};
            g.Ahi = nxt; g.Alo = nxt + 2048;
            g.Bhi = W1t; g.Blo = W1t + 2048;
            g.nchunk = UNITS / 64; g.lda = HROW; g.ldb = WK;
            g.addend = pbuf; g.bias = b1;
            g.outE = nxt + 4096; g.ldo = HROW;
            g.out32 = (t == SEQ - 1) ? h1f : nullptr; g.act = 1;
            gemm_tile<64>(g, cm, cn, sm);
        }
        grid_sync(bar, 2 * t + 1);

        __nv_bfloat16* tmp = cur; cur = nxt; nxt = tmp;
    }
}

// ---------------- consolidated prep kernel -------------------------------------
// grid (64,64,6), block (32,8).
__global__ void prep_all(const float* __restrict__ U0, const float* __restrict__ W1,
                         const float* __restrict__ U1, const float* __restrict__ W0,
                         const int* __restrict__ inputs, const float* __restrict__ emb,
                         __nv_bfloat16* __restrict__ U0t, __nv_bfloat16* __restrict__ W1t,
                         __nv_bfloat16* __restrict__ U1t, __nv_bfloat16* __restrict__ w0t,
                         __nv_bfloat16* __restrict__ xe,  uint32_t* __restrict__ hzero)
{
    __shared__ float tile[32][33];
    int z = blockIdx.z;
    if (z < 3) {
        const float* W = (z == 0) ? U0 : (z == 1) ? W1 : U1;
        __nv_bfloat16* out = (z == 0) ? U0t : (z == 1) ? W1t : U1t;
        int k0 = blockIdx.y * 32, n0 = blockIdx.x * 32;
        #pragma unroll
        for (int r = 0; r < 4; r++)
            tile[threadIdx.y + 8 * r][threadIdx.x] =
                W[(size_t)(k0 + threadIdx.y + 8 * r) * UNITS + n0 + threadIdx.x];
        __syncthreads();
        #pragma unroll
        for (int r = 0; r < 4; r++) {
            int n = n0 + threadIdx.y + 8 * r;
            int k = k0 + threadIdx.x;
            float w = tile[threadIdx.x][threadIdx.y + 8 * r];
            __nv_bfloat16 hi = __float2bfloat16(w);
            __nv_bfloat16 lo = __float2bfloat16(w - __bfloat162float(hi));
            out[(size_t)n * WK + k]         = hi;
            out[(size_t)n * WK + UNITS + k] = lo;
        }
        return;
    }
    int tid = threadIdx.y * 32 + threadIdx.x;
    int bid = blockIdx.y * 64 + blockIdx.x;
    int gid = bid * 256 + tid;
    if (z == 3) {
        if (gid < UNITS * 128) {
            int n = gid >> 7, k = gid & 127;
            float v = (k < EMBED) ? W0[(size_t)k * UNITS + n] : 0.f;
            __nv_bfloat16 hi = __float2bfloat16(v);
            __nv_bfloat16 lo = __float2bfloat16(v - __bfloat162float(hi));
            w0t[(size_t)n * XK + k]       = hi;
            w0t[(size_t)n * XK + 128 + k] = lo;
        }
    } else if (z == 4) {
        for (int w = gid; w < SEQ * BATCH * 128; w += 4096 * 256) {
            int row = w >> 7, k = w & 127;
            int t = row / BATCH, b = row % BATCH;
            int tok = inputs[b * SEQ + t];
            float v = (k < EMBED) ? emb[(size_t)tok * EMBED + k] : 0.f;
            __nv_bfloat16 hi = __float2bfloat16(v);
            __nv_bfloat16 lo = __float2bfloat16(v - __bfloat162float(hi));
            xe[(size_t)row * XK + k]       = hi;
            xe[(size_t)row * XK + 128 + k] = lo;
        }
    } else {
        hzero[gid] = 0u;
    }
}

__global__ void zero_bar_kernel(unsigned* bar) {
    if (threadIdx.x < 2 * SEQ + 8) bar[threadIdx.x] = 0u;
}

__global__ void final_kernel(const float* __restrict__ h1,
                             const float* __restrict__ Wo,
                             const float* __restrict__ bo,
                             float* __restrict__ out) {
    int b = blockIdx.x;
    float s = 0.f;
    for (int i = threadIdx.x; i < UNITS; i += blockDim.x)
        s += h1[b * UNITS + i] * Wo[i];
    for (int off = 16; off; off >>= 1) s += __shfl_down_sync(0xffffffffu, s, off);
    __shared__ float red[8];
    if ((threadIdx.x & 31) == 0) red[threadIdx.x >> 5] = s;
    __syncthreads();
    if (threadIdx.x == 0) {
        float t = 0.f;
        for (int w = 0; w < (int)(blockDim.x >> 5); w++) t += red[w];
        out[b] = 1.f / (1.f + expf(-(t + bo[0])));
    }
}

// ---------------- launch ------------------------------------------------------
extern "C" void kernel_launch(void* const* d_in, const int* in_sizes, int n_in,
                              void* d_out, int out_size)
{
    const int*   inputs = (const int*)  d_in[0];
    const float* emb    = (const float*)d_in[1];
    const float* W0     = (const float*)d_in[2];
    const float* U0     = (const float*)d_in[3];
    const float* b0     = (const float*)d_in[4];
    const float* W1     = (const float*)d_in[5];
    const float* U1     = (const float*)d_in[6];
    const float* b1     = (const float*)d_in[7];
    const float* Wo     = (const float*)d_in[8];
    const float* bo     = (const float*)d_in[9];
    float* out = (float*)d_out;

    __nv_bfloat16 *xe, *w0t, *U0t, *W1t, *U1t, *hbuf;
    float *xw0, *pbuf, *h1f;
    unsigned* bar;
    cudaGetSymbolAddress((void**)&xe,   g_xe);
    cudaGetSymbolAddress((void**)&w0t,  g_w0t);
    cudaGetSymbolAddress((void**)&U0t,  g_U0t);
    cudaGetSymbolAddress((void**)&W1t,  g_W1t);
    cudaGetSymbolAddress((void**)&U1t,  g_U1t);
    cudaGetSymbolAddress((void**)&xw0,  g_xw0);
    cudaGetSymbolAddress((void**)&pbuf, g_p);
    cudaGetSymbolAddress((void**)&hbuf, g_hbuf);
    cudaGetSymbolAddress((void**)&h1f,  g_h1f);
    cudaGetSymbolAddress((void**)&bar,  g_bar);

    // 2 stages x 2 sub-chunks x (A 16KB + B 32KB) = 192KB (BN=128 path)
    const int SMEM = 2 * 2 * (2 * 64 * 128 + 2 * 128 * 128);  // 196608
    cudaFuncSetAttribute(xw0_gemm,
                         cudaFuncAttributeMaxDynamicSharedMemorySize, SMEM);
    cudaFuncSetAttribute(rnn_persistent,
                         cudaFuncAttributeMaxDynamicSharedMemorySize, SMEM);

    // launch 0: all prep
    prep_all<<<dim3(64, 64, 6), dim3(32, 8)>>>(U0, W1, U1, W0, inputs, emb,
                                               U0t, W1t, U1t, w0t, xe,
                                               (uint32_t*)hbuf);

    // launch 1: xw0 = x @ W0 + b0
    {
        Args g{};
        g.Ahi = xe; g.Alo = xe + 128; g.Bhi = w0t; g.Blo = w0t + 128;
        g.nchunk = 2; g.lda = XK; g.ldb = XK;
        g.addend = nullptr; g.bias = b0;
        g.outE = nullptr; g.ldo = 0; g.out32 = xw0; g.act = 0;
        xw0_gemm<<<dim3(UNITS / 128, (SEQ * BATCH) / 64), 512, SMEM>>>(g);
    }

    // launch 2: zero barrier counters
    zero_bar_kernel<<<1, 256>>>(bar);

    // launch 3: persistent time loop (profiled slot)
    rnn_persistent<<<NCTA, 512, SMEM>>>(U0t, W1t, U1t, xw0, b1,
                                        pbuf, hbuf, h1f, bar);

    // launch 4: output head
    final_kernel<<<BATCH, 256>>>(h1f, Wo, bo, out);
}

// round 10
// speedup vs baseline: 1.0441x; 1.0441x over previous
#include <cuda_runtime.h>
#include <cuda_bf16.h>
#include <math.h>
#include <stdint.h>

#define SEQ    80
#define BATCH  256
#define EMBED  100
#define UNITS  2048
#define WK     4096          // weight row: [hi(2048) | lo(2048)]
#define XK     256           // x row: [hi(128 pad) | lo(128 pad)]
#define HROW   8192          // h row: [h0hi|h0lo|h1hi|h1lo]
#define NCTA   128

// ---------------- scratch ----------------------------------------------------
__device__ __nv_bfloat16 g_xe [SEQ * BATCH * XK];
__device__ __nv_bfloat16 g_w0t[UNITS * XK];
__device__ __nv_bfloat16 g_U0t[UNITS * WK];
__device__ __nv_bfloat16 g_W1t[UNITS * WK];
__device__ __nv_bfloat16 g_U1t[UNITS * WK];
__device__ float g_xw0[SEQ * BATCH * UNITS];
__device__ float g_p  [BATCH * UNITS];             // p = h1 @ U1 (fp32)
__device__ __nv_bfloat16 g_hbuf[2][BATCH * HROW];
__device__ float g_h1f[BATCH * UNITS];
__device__ unsigned g_bar[2 * SEQ + 8];            // grid-barrier counters

// ---------------- PTX helpers -------------------------------------------------
__device__ __forceinline__ uint32_t smem_u32(const void* p) {
    uint32_t a;
    asm("{ .reg .u64 t; cvta.to.shared.u64 t, %1; cvt.u32.u64 %0, t; }" : "=r"(a) : "l"(p));
    return a;
}
#define CP_ASYNC16(sp, gp) \
    asm volatile("cp.async.cg.shared.global [%0], [%1], 16;" :: "r"(sp), "l"(gp))
#define CP_COMMIT()  asm volatile("cp.async.commit_group;")
#define CP_WAIT2()   asm volatile("cp.async.wait_group 2;")
#define CP_WAIT0()   asm volatile("cp.async.wait_group 0;")

__device__ __forceinline__ void ldm_x4(uint32_t* r, uint32_t addr) {
    asm volatile("ldmatrix.sync.aligned.m8n8.x4.shared.b16 {%0,%1,%2,%3}, [%4];"
                 : "=r"(r[0]), "=r"(r[1]), "=r"(r[2]), "=r"(r[3]) : "r"(addr));
}
__device__ __forceinline__ void mma_bf16(float* d, const uint32_t* a, const uint32_t* b) {
    asm volatile("mma.sync.aligned.m16n8k16.row.col.f32.bf16.bf16.f32 "
                 "{%0,%1,%2,%3}, {%4,%5,%6,%7}, {%8,%9}, {%0,%1,%2,%3};"
                 : "+f"(d[0]), "+f"(d[1]), "+f"(d[2]), "+f"(d[3])
                 : "r"(a[0]), "r"(a[1]), "r"(a[2]), "r"(a[3]), "r"(b[0]), "r"(b[1]));
}

__device__ __forceinline__ int swz128(int row, int c16) {
    return row * 128 + ((c16 ^ (row & 7)) << 4);
}

// grid-wide barrier: one counter slot per use, all NCTA CTAs must arrive.
__device__ __forceinline__ void grid_sync(unsigned* bar, int s) {
    __syncthreads();
    if (threadIdx.x == 0) {
        __threadfence();
        atomicAdd(&bar[s], 1u);
        while (*((volatile unsigned*)&bar[s]) < NCTA) __nanosleep(32);
    }
    __syncthreads();
}

// ---------------- split-GEMM tile (3-term hi/lo) ------------------------------
struct Args {
    const __nv_bfloat16 *Ahi, *Alo, *Bhi, *Blo;
    int  nchunk;                  // K / 64
    long lda, ldb;
    const float* addend;          // [M,2048] or null (read via __ldcg)
    const float* bias;            // [2048] or null
    __nv_bfloat16* outE;          // hi @ col n, lo @ col n+2048; or null
    long ldo;
    float* out32;                 // [M,2048] or null
    int  act;
};

template<int NROWS>
__device__ __forceinline__ void load_rows(const __nv_bfloat16* src, long ld,
                                          int rbase, int kc, char* dst, int tid) {
    #pragma unroll
    for (int i = 0; i < NROWS * 8 / 256; i++) {
        int s = tid + i * 256;
        int row = s >> 3, c16 = s & 7;
        const void* g = src + (size_t)(rbase + row) * ld + kc * 64 + c16 * 8;
        CP_ASYNC16(smem_u32(dst + swz128(row, c16)), g);
    }
}

// BM=64, BK=64. 256 threads, 8 warps (2m x 4n); warp tile 32 x (BN/4).
// 4-stage cp.async ring + register fragment double-buffer across ks +
// pass-reordered mmas (8-wide accumulator ILP).
template<int BN>
__device__ void gemm_tile(const Args& g, int cm, int cn, char* sm)
{
    constexpr int NI = BN / 64;
    constexpr int TILE_A = 64 * 128;
    constexpr int TILE_B = BN * 128;
    constexpr int STAGE  = 2 * TILE_A + 2 * TILE_B;

    int tid  = threadIdx.x;
    int lane = tid & 31;
    int wid  = tid >> 5;
    int wm   = wid >> 2;
    int wn   = wid & 3;

    float acc[2][2 * NI][4];
    #pragma unroll
    for (int i = 0; i < 2; i++)
        #pragma unroll
        for (int j = 0; j < 2 * NI; j++)
            #pragma unroll
            for (int k = 0; k < 4; k++) acc[i][j][k] = 0.f;

    int NC = g.nchunk;

    auto issue = [&](int c) {
        char* st = sm + (c & 3) * STAGE;
        load_rows<64>(g.Ahi, g.lda, cm, c, st,              tid);
        load_rows<64>(g.Alo, g.lda, cm, c, st + TILE_A,     tid);
        load_rows<BN>(g.Bhi, g.ldb, cn, c, st + 2 * TILE_A, tid);
        load_rows<BN>(g.Blo, g.ldb, cn, c, st + 2 * TILE_A + TILE_B, tid);
        CP_COMMIT();
    };

    issue(0);
    if (NC > 1) issue(1);
    if (NC > 2) issue(2);

    // fragment buffers (double-buffered over ks)
    uint32_t ahi[2][2][4], alo[2][2][4], bhi[2][NI][4], blo[2][NI][4];

    for (int c = 0; c < NC; c++) {
        if (c + 2 < NC) { CP_WAIT2(); } else { CP_WAIT0(); }
        __syncthreads();
        if (c + 3 < NC) issue(c + 3);

        char* cs = sm + (c & 3) * STAGE;
        char* pa_hi = cs;
        char* pa_lo = cs + TILE_A;
        char* pb_hi = cs + 2 * TILE_A;
        char* pb_lo = cs + 2 * TILE_A + TILE_B;

        auto load_frags = [&](int buf, int ks) {
            #pragma unroll
            for (int mi = 0; mi < 2; mi++) {
                int arow = wm * 32 + mi * 16 + (lane & 15);
                int ac   = ks * 2 + (lane >> 4);
                ldm_x4(ahi[buf][mi], smem_u32(pa_hi + swz128(arow, ac)));
                ldm_x4(alo[buf][mi], smem_u32(pa_lo + swz128(arow, ac)));
            }
            #pragma unroll
            for (int np = 0; np < NI; np++) {
                int brow = wn * (BN / 4) + np * 16 + ((lane & 16) ? 8 : 0) + (lane & 7);
                int bc   = ks * 2 + ((lane >> 3) & 1);
                ldm_x4(bhi[buf][np], smem_u32(pb_hi + swz128(brow, bc)));
                ldm_x4(blo[buf][np], smem_u32(pb_lo + swz128(brow, bc)));
            }
        };

        load_frags(0, 0);

        #pragma unroll
        for (int ks = 0; ks < 4; ks++) {
            int cur = ks & 1;
            if (ks < 3) load_frags(cur ^ 1, ks + 1);   // overlap with mmas below

            // pass 1: ahi*bhi across all accumulator tiles (8-wide ILP)
            #pragma unroll
            for (int mi = 0; mi < 2; mi++)
                #pragma unroll
                for (int np = 0; np < NI; np++)
                    #pragma unroll
                    for (int h = 0; h < 2; h++)
                        mma_bf16(acc[mi][np * 2 + h], ahi[cur][mi], &bhi[cur][np][h * 2]);
            // pass 2: alo*bhi
            #pragma unroll
            for (int mi = 0; mi < 2; mi++)
                #pragma unroll
                for (int np = 0; np < NI; np++)
                    #pragma unroll
                    for (int h = 0; h < 2; h++)
                        mma_bf16(acc[mi][np * 2 + h], alo[cur][mi], &bhi[cur][np][h * 2]);
            // pass 3: ahi*blo
            #pragma unroll
            for (int mi = 0; mi < 2; mi++)
                #pragma unroll
                for (int np = 0; np < NI; np++)
                    #pragma unroll
                    for (int h = 0; h < 2; h++)
                        mma_bf16(acc[mi][np * 2 + h], ahi[cur][mi], &blo[cur][np][h * 2]);
        }
        // buffer (c&3) reused by issue(c+4); the sync at iter c+1 precedes it.
    }

    // epilogue
    int r0 = cm + wm * 32 + (lane >> 2);
    int c0 = cn + wn * (BN / 4) + (lane & 3) * 2;
    #pragma unroll
    for (int mi = 0; mi < 2; mi++) {
        #pragma unroll
        for (int ni = 0; ni < 2 * NI; ni++) {
            #pragma unroll
            for (int h8 = 0; h8 < 2; h8++) {
                int row = r0 + mi * 16 + h8 * 8;
                int col = c0 + ni * 8;
                float v0 = acc[mi][ni][h8 * 2 + 0];
                float v1 = acc[mi][ni][h8 * 2 + 1];
                if (g.addend) {
                    float2 ad = __ldcg((const float2*)&g.addend[(size_t)row * UNITS + col]);
                    v0 += ad.x; v1 += ad.y;
                }
                if (g.bias) {
                    float2 bi = *(const float2*)&g.bias[col];
                    v0 += bi.x; v1 += bi.y;
                }
                if (g.act) { v0 = tanhf(v0); v1 = tanhf(v1); }
                if (g.out32)
                    *(float2*)&g.out32[(size_t)row * UNITS + col] = make_float2(v0, v1);
                if (g.outE) {
                    __nv_bfloat16 h0 = __float2bfloat16(v0);
                    __nv_bfloat16 h1 = __float2bfloat16(v1);
                    __nv_bfloat16 l0 = __float2bfloat16(v0 - __bfloat162float(h0));
                    __nv_bfloat16 l1 = __float2bfloat16(v1 - __bfloat162float(h1));
                    __nv_bfloat162 hp; hp.x = h0; hp.y = h1;
                    __nv_bfloat162 lp; lp.x = l0; lp.y = l1;
                    *(__nv_bfloat162*)&g.outE[(size_t)row * g.ldo + col]         = hp;
                    *(__nv_bfloat162*)&g.outE[(size_t)row * g.ldo + UNITS + col] = lp;
                }
            }
        }
    }
}

// ---------------- standalone GEMM kernel (xw0 precompute) ---------------------
__global__ void __launch_bounds__(256)
xw0_gemm(Args g)
{
    extern __shared__ __align__(16) char sm[];
    gemm_tile<128>(g, blockIdx.y * 64, blockIdx.x * 128, sm);
}

// ---------------- persistent RNN time loop ------------------------------------
__global__ void __launch_bounds__(256)
rnn_persistent(const __nv_bfloat16* __restrict__ U0t,
               const __nv_bfloat16* __restrict__ W1t,
               const __nv_bfloat16* __restrict__ U1t,
               const float* __restrict__ xw0,
               const float* __restrict__ b1,
               float* __restrict__ pbuf,
               __nv_bfloat16* __restrict__ hbuf,
               float* __restrict__ h1f,
               unsigned* __restrict__ bar)
{
    extern __shared__ __align__(16) char sm[];
    int cid = blockIdx.x;

    __nv_bfloat16* cur = hbuf;
    __nv_bfloat16* nxt = hbuf + (size_t)BATCH * HROW;

    for (int t = 0; t < SEQ; t++) {
        // phase A: 64 CTAs -> h0' = tanh(xw0_t + h0@U0); 64 CTAs -> p = h1@U1
        {
            int unit = cid >> 6;
            int id   = cid & 63;
            int cm = (id >> 4) * 64;     // 0..3 -> 4 m-tiles
            int cn = (id & 15) * 128;    // 0..15 -> 16 n-tiles

            Args g{};
            g.nchunk = UNITS / 64; g.lda = HROW; g.ldb = WK;
            if (unit == 0) {
                g.Ahi = cur;  g.Alo = cur + 2048;
                g.Bhi = U0t;  g.Blo = U0t + 2048;
                g.addend = xw0 + (size_t)t * BATCH * UNITS; g.bias = nullptr;
                g.outE = nxt; g.ldo = HROW; g.out32 = nullptr; g.act = 1;
            } else {
                g.Ahi = cur + 4096; g.Alo = cur + 6144;
                g.Bhi = U1t;        g.Blo = U1t + 2048;
                g.addend = nullptr; g.bias = nullptr;
                g.outE = nullptr; g.ldo = 0; g.out32 = pbuf; g.act = 0;
            }
            gemm_tile<128>(g, cm, cn, sm);
        }
        grid_sync(bar, 2 * t);

        // phase B: 128 CTAs -> h1' = tanh(h0'@W1 + p + b1)
        {
            int cm = (cid >> 5) * 64;    // 0..3
            int cn = (cid & 31) * 64;    // 0..31

            Args g{};
            g.Ahi = nxt; g.Alo = nxt + 2048;
            g.Bhi = W1t; g.Blo = W1t + 2048;
            g.nchunk = UNITS / 64; g.lda = HROW; g.ldb = WK;
            g.addend = pbuf; g.bias = b1;
            g.outE = nxt + 4096; g.ldo = HROW;
            g.out32 = (t == SEQ - 1) ? h1f : nullptr; g.act = 1;
            gemm_tile<64>(g, cm, cn, sm);
        }
        grid_sync(bar, 2 * t + 1);

        __nv_bfloat16* tmp = cur; cur = nxt; nxt = tmp;
    }
}

// ---------------- consolidated prep kernel -------------------------------------
// grid (64,64,6), block (32,8).
__global__ void prep_all(const float* __restrict__ U0, const float* __restrict__ W1,
                         const float* __restrict__ U1, const float* __restrict__ W0,
                         const int* __restrict__ inputs, const float* __restrict__ emb,
                         __nv_bfloat16* __restrict__ U0t, __nv_bfloat16* __restrict__ W1t,
                         __nv_bfloat16* __restrict__ U1t, __nv_bfloat16* __restrict__ w0t,
                         __nv_bfloat16* __restrict__ xe,  uint32_t* __restrict__ hzero)
{
    __shared__ float tile[32][33];
    int z = blockIdx.z;
    if (z < 3) {
        const float* W = (z == 0) ? U0 : (z == 1) ? W1 : U1;
        __nv_bfloat16* out = (z == 0) ? U0t : (z == 1) ? W1t : U1t;
        int k0 = blockIdx.y * 32, n0 = blockIdx.x * 32;
        #pragma unroll
        for (int r = 0; r < 4; r++)
            tile[threadIdx.y + 8 * r][threadIdx.x] =
                W[(size_t)(k0 + threadIdx.y + 8 * r) * UNITS + n0 + threadIdx.x];
        __syncthreads();
        #pragma unroll
        for (int r = 0; r < 4; r++) {
            int n = n0 + threadIdx.y + 8 * r;
            int k = k0 + threadIdx.x;
            float w = tile[threadIdx.x][threadIdx.y + 8 * r];
            __nv_bfloat16 hi = __float2bfloat16(w);
            __nv_bfloat16 lo = __float2bfloat16(w - __bfloat162float(hi));
            out[(size_t)n * WK + k]         = hi;
            out[(size_t)n * WK + UNITS + k] = lo;
        }
        return;
    }
    int tid = threadIdx.y * 32 + threadIdx.x;
    int bid = blockIdx.y * 64 + blockIdx.x;
    int gid = bid * 256 + tid;
    if (z == 3) {
        if (gid < UNITS * 128) {
            int n = gid >> 7, k = gid & 127;
            float v = (k < EMBED) ? W0[(size_t)k * UNITS + n] : 0.f;
            __nv_bfloat16 hi = __float2bfloat16(v);
            __nv_bfloat16 lo = __float2bfloat16(v - __bfloat162float(hi));
            w0t[(size_t)n * XK + k]       = hi;
            w0t[(size_t)n * XK + 128 + k] = lo;
        }
    } else if (z == 4) {
        for (int w = gid; w < SEQ * BATCH * 128; w += 4096 * 256) {
            int row = w >> 7, k = w & 127;
            int t = row / BATCH, b = row % BATCH;
            int tok = inputs[b * SEQ + t];
            float v = (k < EMBED) ? emb[(size_t)tok * EMBED + k] : 0.f;
            __nv_bfloat16 hi = __float2bfloat16(v);
            __nv_bfloat16 lo = __float2bfloat16(v - __bfloat162float(hi));
            xe[(size_t)row * XK + k]       = hi;
            xe[(size_t)row * XK + 128 + k] = lo;
        }
    } else {
        hzero[gid] = 0u;
    }
}

__global__ void zero_bar_kernel(unsigned* bar) {
    if (threadIdx.x < 2 * SEQ + 8) bar[threadIdx.x] = 0u;
}

__global__ void final_kernel(const float* __restrict__ h1,
                             const float* __restrict__ Wo,
                             const float* __restrict__ bo,
                             float* __restrict__ out) {
    int b = blockIdx.x;
    float s = 0.f;
    for (int i = threadIdx.x; i < UNITS; i += blockDim.x)
        s += h1[b * UNITS + i] * Wo[i];
    for (int off = 16; off; off >>= 1) s += __shfl_down_sync(0xffffffffu, s, off);
    __shared__ float red[8];
    if ((threadIdx.x & 31) == 0) red[threadIdx.x >> 5] = s;
    __syncthreads();
    if (threadIdx.x == 0) {
        float t = 0.f;
        for (int w = 0; w < (int)(blockDim.x >> 5); w++) t += red[w];
        out[b] = 1.f / (1.f + expf(-(t + bo[0])));
    }
}

// ---------------- launch ------------------------------------------------------
extern "C" void kernel_launch(void* const* d_in, const int* in_sizes, int n_in,
                              void* d_out, int out_size)
{
    const int*   inputs = (const int*)  d_in[0];
    const float* emb    = (const float*)d_in[1];
    const float* W0     = (const float*)d_in[2];
    const float* U0     = (const float*)d_in[3];
    const float* b0     = (const float*)d_in[4];
    const float* W1     = (const float*)d_in[5];
    const float* U1     = (const float*)d_in[6];
    const float* b1     = (const float*)d_in[7];
    const float* Wo     = (const float*)d_in[8];
    const float* bo     = (const float*)d_in[9];
    float* out = (float*)d_out;

    __nv_bfloat16 *xe, *w0t, *U0t, *W1t, *U1t, *hbuf;
    float *xw0, *pbuf, *h1f;
    unsigned* bar;
    cudaGetSymbolAddress((void**)&xe,   g_xe);
    cudaGetSymbolAddress((void**)&w0t,  g_w0t);
    cudaGetSymbolAddress((void**)&U0t,  g_U0t);
    cudaGetSymbolAddress((void**)&W1t,  g_W1t);
    cudaGetSymbolAddress((void**)&U1t,  g_U1t);
    cudaGetSymbolAddress((void**)&xw0,  g_xw0);
    cudaGetSymbolAddress((void**)&pbuf, g_p);
    cudaGetSymbolAddress((void**)&hbuf, g_hbuf);
    cudaGetSymbolAddress((void**)&h1f,  g_h1f);
    cudaGetSymbolAddress((void**)&bar,  g_bar);

    const int SMEM = 4 * (2 * 64 * 128 + 2 * 128 * 128);   // 196608 (4 stages)
    cudaFuncSetAttribute(xw0_gemm,
                         cudaFuncAttributeMaxDynamicSharedMemorySize, SMEM);
    cudaFuncSetAttribute(rnn_persistent,
                         cudaFuncAttributeMaxDynamicSharedMemorySize, SMEM);

    // launch 0: all prep
    prep_all<<<dim3(64, 64, 6), dim3(32, 8)>>>(U0, W1, U1, W0, inputs, emb,
                                               U0t, W1t, U1t, w0t, xe,
                                               (uint32_t*)hbuf);

    // launch 1: xw0 = x @ W0 + b0
    {
        Args g{};
        g.Ahi = xe; g.Alo = xe + 128; g.Bhi = w0t; g.Blo = w0t + 128;
        g.nchunk = 2; g.lda = XK; g.ldb = XK;
        g.addend = nullptr; g.bias = b0;
        g.outE = nullptr; g.ldo = 0; g.out32 = xw0; g.act = 0;
        xw0_gemm<<<dim3(UNITS / 128, (SEQ * BATCH) / 64), 256, SMEM>>>(g);
    }

    // launch 2: zero barrier counters
    zero_bar_kernel<<<1, 256>>>(bar);

    // launch 3: persistent time loop (profiled slot)
    rnn_persistent<<<NCTA, 256, SMEM>>>(U0t, W1t, U1t, xw0, b1,
                                        pbuf, hbuf, h1f, bar);

    // launch 4: output head
    final_kernel<<<BATCH, 256>>>(h1f, Wo, bo, out);
}